// round 1
// baseline (speedup 1.0000x reference)
#include <cuda_runtime.h>
#include <math.h>

#define D_MODEL 1024
#define N_TOK   8192      // 8 * 1024
#define FF_DIM  4096
#define N_HEAD  16
#define HEAD_D  64

// ---------------- scratch (no allocations allowed) ----------------
__device__ float g_h  [N_TOK * D_MODEL];   // LN output (reused for ln1 & ln2)
__device__ float g_qkv[N_TOK * 3 * D_MODEL];
__device__ float g_ctx[N_TOK * D_MODEL];
__device__ float g_x2 [N_TOK * D_MODEL];   // after attention residual
__device__ float g_ff [N_TOK * FF_DIM];

// ---------------- LayerNorm: one block per row ----------------
__global__ void __launch_bounds__(256) ln_kernel(const float* __restrict__ x,
                                                 const float* __restrict__ g,
                                                 const float* __restrict__ b,
                                                 float* __restrict__ out) {
    int row = blockIdx.x;
    int t = threadIdx.x;
    const float* xr = x + (size_t)row * D_MODEL;
    float4 xv = ((const float4*)xr)[t];

    float s  = xv.x + xv.y + xv.z + xv.w;
    float sq = xv.x*xv.x + xv.y*xv.y + xv.z*xv.z + xv.w*xv.w;
    #pragma unroll
    for (int o = 16; o > 0; o >>= 1) {
        s  += __shfl_xor_sync(0xffffffffu, s,  o);
        sq += __shfl_xor_sync(0xffffffffu, sq, o);
    }
    __shared__ float red[2][8];
    int wid = t >> 5, lane = t & 31;
    if (lane == 0) { red[0][wid] = s; red[1][wid] = sq; }
    __syncthreads();
    float tot = 0.f, tot2 = 0.f;
    #pragma unroll
    for (int w = 0; w < 8; ++w) { tot += red[0][w]; tot2 += red[1][w]; }
    float mu = tot * (1.0f / D_MODEL);
    float var = tot2 * (1.0f / D_MODEL) - mu * mu;
    float rstd = rsqrtf(var + 1e-6f);

    float4 gv = ((const float4*)g)[t];
    float4 bv = ((const float4*)b)[t];
    float4 ov;
    ov.x = (xv.x - mu) * rstd * gv.x + bv.x;
    ov.y = (xv.y - mu) * rstd * gv.y + bv.y;
    ov.z = (xv.z - mu) * rstd * gv.z + bv.z;
    ov.w = (xv.w - mu) * rstd * gv.w + bv.w;
    ((float4*)(out + (size_t)row * D_MODEL))[t] = ov;
}

// ---------------- GEMM: C[M,N] = A[M,K] @ B[N,K]^T + bias (+epi) ----------------
// EPI: 0 = bias only, 1 = bias + exact GELU, 2 = bias + residual add
#define BM 128
#define BN 128
#define BK 16

__device__ __forceinline__ float gelu_exact(float v) {
    return 0.5f * v * (1.0f + erff(v * 0.70710678118654752440f));
}

template<int EPI>
__global__ void __launch_bounds__(256) gemm_nt(const float* __restrict__ A,
                                               const float* __restrict__ Bw,
                                               const float* __restrict__ bias,
                                               const float* __restrict__ res,
                                               float* __restrict__ C,
                                               int M, int N, int K) {
    __shared__ float As[BK][BM];
    __shared__ float Bs[BK][BN];

    int tid = threadIdx.x;
    int n0 = blockIdx.x * BN;
    int m0 = blockIdx.y * BM;
    int tx = tid & 15;        // 0..15  (n)
    int ty = tid >> 4;        // 0..15  (m)

    float acc[8][8];
    #pragma unroll
    for (int i = 0; i < 8; ++i)
        #pragma unroll
        for (int j = 0; j < 8; ++j) acc[i][j] = 0.f;

    int ldRow = tid >> 2;          // 0..63
    int ldK   = (tid & 3) * 4;     // 0,4,8,12
    const float* Aptr = A  + (size_t)(m0 + ldRow) * K + ldK;
    const float* Bptr = Bw + (size_t)(n0 + ldRow) * K + ldK;
    size_t halfA = (size_t)64 * K;

    for (int k0 = 0; k0 < K; k0 += BK) {
        float4 a0 = *(const float4*)(Aptr + k0);
        float4 a1 = *(const float4*)(Aptr + halfA + k0);
        float4 b0 = *(const float4*)(Bptr + k0);
        float4 b1 = *(const float4*)(Bptr + halfA + k0);

        __syncthreads();
        As[ldK+0][ldRow] = a0.x; As[ldK+1][ldRow] = a0.y;
        As[ldK+2][ldRow] = a0.z; As[ldK+3][ldRow] = a0.w;
        As[ldK+0][ldRow+64] = a1.x; As[ldK+1][ldRow+64] = a1.y;
        As[ldK+2][ldRow+64] = a1.z; As[ldK+3][ldRow+64] = a1.w;
        Bs[ldK+0][ldRow] = b0.x; Bs[ldK+1][ldRow] = b0.y;
        Bs[ldK+2][ldRow] = b0.z; Bs[ldK+3][ldRow] = b0.w;
        Bs[ldK+0][ldRow+64] = b1.x; Bs[ldK+1][ldRow+64] = b1.y;
        Bs[ldK+2][ldRow+64] = b1.z; Bs[ldK+3][ldRow+64] = b1.w;
        __syncthreads();

        #pragma unroll
        for (int k = 0; k < BK; ++k) {
            float4 am0 = *(const float4*)&As[k][ty*8];
            float4 am1 = *(const float4*)&As[k][ty*8+4];
            float4 bn0 = *(const float4*)&Bs[k][tx*8];
            float4 bn1 = *(const float4*)&Bs[k][tx*8+4];
            float av[8] = {am0.x, am0.y, am0.z, am0.w, am1.x, am1.y, am1.z, am1.w};
            float bv[8] = {bn0.x, bn0.y, bn0.z, bn0.w, bn1.x, bn1.y, bn1.z, bn1.w};
            #pragma unroll
            for (int i = 0; i < 8; ++i)
                #pragma unroll
                for (int j = 0; j < 8; ++j)
                    acc[i][j] = fmaf(av[i], bv[j], acc[i][j]);
        }
    }

    #pragma unroll
    for (int i = 0; i < 8; ++i) {
        int m = m0 + ty*8 + i;
        #pragma unroll
        for (int j = 0; j < 8; ++j) {
            int n = n0 + tx*8 + j;
            float v = acc[i][j] + bias[n];
            if (EPI == 1) v = gelu_exact(v);
            if (EPI == 2) v += res[(size_t)m * N + n];
            C[(size_t)m * N + n] = v;
        }
    }
}

// ---------------- Flash attention ----------------
// grid: (S/64, H, B), block: 256 threads.
// Thread t: q-row r = t/4, quad lane q = t%4.
// Scores: thread owns cols {4c+q}; ctx dims: thread owns d = q*16 .. q*16+15.
#define APITCH 68

__global__ void __launch_bounds__(256) attn_kernel(const float* __restrict__ qkv,
                                                   float* __restrict__ ctx) {
    extern __shared__ float sm[];
    float* Qs = sm;
    float* Ks = Qs + 64 * APITCH;
    float* Vs = Ks + 64 * APITCH;
    float* Ps = Vs + 64 * APITCH;

    int t = threadIdx.x;
    int b = blockIdx.z, h = blockIdx.y;
    int s0 = blockIdx.x * 64;
    int r = t >> 2, q = t & 3;

    // token stride in qkv = 3*1024 floats; sel offsets 0/1024/2048; head offset h*64
    const float* qbase = qkv + ((size_t)(b * 1024 + s0) * 3072) + h * HEAD_D;
    const float* kbase = qkv + ((size_t)b * 1024 * 3072) + 1024 + h * HEAD_D;
    const float* vbase = qkv + ((size_t)b * 1024 * 3072) + 2048 + h * HEAD_D;

    #pragma unroll
    for (int p = 0; p < 4; ++p) {
        int j = t + 256 * p;            // float4 index 0..1023
        int row = j >> 4, c4 = j & 15;
        *(float4*)&Qs[row * APITCH + c4 * 4] =
            *(const float4*)(qbase + (size_t)row * 3072 + c4 * 4);
    }

    float mrun = -1e30f, l = 0.f;
    float o[16];
    #pragma unroll
    for (int i = 0; i < 16; ++i) o[i] = 0.f;
    const float scale = 0.125f;   // 1/sqrt(64)

    for (int j0 = 0; j0 < 1024; j0 += 64) {
        __syncthreads();   // previous P/V use complete before overwrite
        #pragma unroll
        for (int p = 0; p < 4; ++p) {
            int j = t + 256 * p;
            int row = j >> 4, c4 = j & 15;
            *(float4*)&Ks[row * APITCH + c4 * 4] =
                *(const float4*)(kbase + (size_t)(j0 + row) * 3072 + c4 * 4);
            *(float4*)&Vs[row * APITCH + c4 * 4] =
                *(const float4*)(vbase + (size_t)(j0 + row) * 3072 + c4 * 4);
        }
        __syncthreads();

        float s[16];
        #pragma unroll
        for (int c = 0; c < 16; ++c) s[c] = 0.f;
        #pragma unroll
        for (int d4 = 0; d4 < 16; ++d4) {
            float4 qv = *(const float4*)&Qs[r * APITCH + d4 * 4];
            #pragma unroll
            for (int c = 0; c < 16; ++c) {
                float4 kv = *(const float4*)&Ks[(c * 4 + q) * APITCH + d4 * 4];
                s[c] += qv.x*kv.x + qv.y*kv.y + qv.z*kv.z + qv.w*kv.w;
            }
        }

        float mloc = -1e30f;
        #pragma unroll
        for (int c = 0; c < 16; ++c) { s[c] *= scale; mloc = fmaxf(mloc, s[c]); }
        mloc = fmaxf(mloc, __shfl_xor_sync(0xffffffffu, mloc, 1));
        mloc = fmaxf(mloc, __shfl_xor_sync(0xffffffffu, mloc, 2));
        float mnew = fmaxf(mrun, mloc);
        float alpha = __expf(mrun - mnew);

        float psum = 0.f;
        #pragma unroll
        for (int c = 0; c < 16; ++c) {
            float pv = __expf(s[c] - mnew);
            psum += pv;
            Ps[r * APITCH + c * 4 + q] = pv;
        }
        psum += __shfl_xor_sync(0xffffffffu, psum, 1);
        psum += __shfl_xor_sync(0xffffffffu, psum, 2);
        l = l * alpha + psum;
        mrun = mnew;
        #pragma unroll
        for (int i = 0; i < 16; ++i) o[i] *= alpha;
        __syncthreads();

        #pragma unroll 4
        for (int c2 = 0; c2 < 64; ++c2) {
            float pv = Ps[r * APITCH + c2];
            #pragma unroll
            for (int i4 = 0; i4 < 4; ++i4) {
                float4 vv = *(const float4*)&Vs[c2 * APITCH + q * 16 + i4 * 4];
                o[i4*4+0] = fmaf(pv, vv.x, o[i4*4+0]);
                o[i4*4+1] = fmaf(pv, vv.y, o[i4*4+1]);
                o[i4*4+2] = fmaf(pv, vv.z, o[i4*4+2]);
                o[i4*4+3] = fmaf(pv, vv.w, o[i4*4+3]);
            }
        }
    }

    float inv = 1.0f / l;
    float* outp = ctx + ((size_t)(b * 1024 + s0 + r) * D_MODEL) + h * HEAD_D + q * 16;
    #pragma unroll
    for (int i4 = 0; i4 < 4; ++i4) {
        float4 w;
        w.x = o[i4*4+0] * inv; w.y = o[i4*4+1] * inv;
        w.z = o[i4*4+2] * inv; w.w = o[i4*4+3] * inv;
        *(float4*)(outp + i4 * 4) = w;
    }
}

// ---------------- launch ----------------
extern "C" void kernel_launch(void* const* d_in, const int* in_sizes, int n_in,
                              void* d_out, int out_size) {
    const float* x      = (const float*)d_in[0];
    const float* qkv_w  = (const float*)d_in[1];
    const float* qkv_b  = (const float*)d_in[2];
    const float* proj_w = (const float*)d_in[3];
    const float* proj_b = (const float*)d_in[4];
    const float* fc1_w  = (const float*)d_in[5];
    const float* fc1_b  = (const float*)d_in[6];
    const float* fc2_w  = (const float*)d_in[7];
    const float* fc2_b  = (const float*)d_in[8];
    const float* ln1_g  = (const float*)d_in[9];
    const float* ln1_b  = (const float*)d_in[10];
    const float* ln2_g  = (const float*)d_in[11];
    const float* ln2_b  = (const float*)d_in[12];
    float* out = (float*)d_out;

    float *h, *qkv, *ctx, *x2, *ff;
    cudaGetSymbolAddress((void**)&h,   g_h);
    cudaGetSymbolAddress((void**)&qkv, g_qkv);
    cudaGetSymbolAddress((void**)&ctx, g_ctx);
    cudaGetSymbolAddress((void**)&x2,  g_x2);
    cudaGetSymbolAddress((void**)&ff,  g_ff);

    int attn_smem = 4 * 64 * APITCH * (int)sizeof(float);   // 69632 B
    cudaFuncSetAttribute(attn_kernel, cudaFuncAttributeMaxDynamicSharedMemorySize,
                         attn_smem);

    // 1. LN1
    ln_kernel<<<N_TOK, 256>>>(x, ln1_g, ln1_b, h);
    // 2. QKV = h @ qkv_w^T + qkv_b
    gemm_nt<0><<<dim3(3 * D_MODEL / BN, N_TOK / BM), 256>>>(
        h, qkv_w, qkv_b, nullptr, qkv, N_TOK, 3 * D_MODEL, D_MODEL);
    // 3. attention -> ctx
    attn_kernel<<<dim3(1024 / 64, N_HEAD, 8), 256, attn_smem>>>(qkv, ctx);
    // 4. x2 = x + ctx @ proj_w^T + proj_b
    gemm_nt<2><<<dim3(D_MODEL / BN, N_TOK / BM), 256>>>(
        ctx, proj_w, proj_b, x, x2, N_TOK, D_MODEL, D_MODEL);
    // 5. LN2
    ln_kernel<<<N_TOK, 256>>>(x2, ln2_g, ln2_b, h);
    // 6. ff = gelu(h @ fc1_w^T + fc1_b)
    gemm_nt<1><<<dim3(FF_DIM / BN, N_TOK / BM), 256>>>(
        h, fc1_w, fc1_b, nullptr, ff, N_TOK, FF_DIM, D_MODEL);
    // 7. out = x2 + ff @ fc2_w^T + fc2_b
    gemm_nt<2><<<dim3(D_MODEL / BN, N_TOK / BM), 256>>>(
        ff, fc2_w, fc2_b, x2, out, N_TOK, D_MODEL, FF_DIM);
}

// round 2
// speedup vs baseline: 1.6764x; 1.6764x over previous
#include <cuda_runtime.h>
#include <math.h>
#include <stdint.h>

#define D_MODEL 1024
#define N_TOK   8192      // 8 * 1024
#define FF_DIM  4096
#define N_HEAD  16
#define HEAD_D  64

// ---------------- scratch (no allocations allowed) ----------------
__device__ float g_h  [N_TOK * D_MODEL];
__device__ float g_qkv[N_TOK * 3 * D_MODEL];
__device__ float g_ctx[N_TOK * D_MODEL];
__device__ float g_x2 [N_TOK * D_MODEL];
__device__ float g_ff [N_TOK * FF_DIM];

// ---------------- LayerNorm ----------------
__global__ void __launch_bounds__(256) ln_kernel(const float* __restrict__ x,
                                                 const float* __restrict__ g,
                                                 const float* __restrict__ b,
                                                 float* __restrict__ out) {
    int row = blockIdx.x;
    int t = threadIdx.x;
    const float* xr = x + (size_t)row * D_MODEL;
    float4 xv = ((const float4*)xr)[t];

    float s  = xv.x + xv.y + xv.z + xv.w;
    float sq = xv.x*xv.x + xv.y*xv.y + xv.z*xv.z + xv.w*xv.w;
    #pragma unroll
    for (int o = 16; o > 0; o >>= 1) {
        s  += __shfl_xor_sync(0xffffffffu, s,  o);
        sq += __shfl_xor_sync(0xffffffffu, sq, o);
    }
    __shared__ float red[2][8];
    int wid = t >> 5, lane = t & 31;
    if (lane == 0) { red[0][wid] = s; red[1][wid] = sq; }
    __syncthreads();
    float tot = 0.f, tot2 = 0.f;
    #pragma unroll
    for (int w = 0; w < 8; ++w) { tot += red[0][w]; tot2 += red[1][w]; }
    float mu = tot * (1.0f / D_MODEL);
    float var = tot2 * (1.0f / D_MODEL) - mu * mu;
    float rstd = rsqrtf(var + 1e-6f);

    float4 gv = ((const float4*)g)[t];
    float4 bv = ((const float4*)b)[t];
    float4 ov;
    ov.x = (xv.x - mu) * rstd * gv.x + bv.x;
    ov.y = (xv.y - mu) * rstd * gv.y + bv.y;
    ov.z = (xv.z - mu) * rstd * gv.z + bv.z;
    ov.w = (xv.w - mu) * rstd * gv.w + bv.w;
    ((float4*)(out + (size_t)row * D_MODEL))[t] = ov;
}

// ---------------- TF32 tensor-core GEMM ----------------
// C[M,N] = A[M,K] @ B[N,K]^T + bias (+ epi)
// EPI: 0 = bias, 1 = bias+GELU(exact), 2 = bias+residual
#define BM 128
#define BN 128
#define BK 16
#define SPITCH 20   // floats per smem row; (20*r + c) mod 32 hits all 32 banks

__device__ __forceinline__ float gelu_exact(float v) {
    return 0.5f * v * (1.0f + erff(v * 0.70710678118654752440f));
}

__device__ __forceinline__ float tf32r(float x) {
    uint32_t u;
    asm("cvt.rna.tf32.f32 %0, %1;" : "=r"(u) : "f"(x));
    return __uint_as_float(u);
}
__device__ __forceinline__ float4 tf32r4(float4 v) {
    v.x = tf32r(v.x); v.y = tf32r(v.y); v.z = tf32r(v.z); v.w = tf32r(v.w);
    return v;
}

__device__ __forceinline__ void mma_tf32(float d[4], uint32_t a0, uint32_t a1,
                                         uint32_t a2, uint32_t a3,
                                         uint32_t b0, uint32_t b1) {
    asm volatile(
        "mma.sync.aligned.m16n8k8.row.col.f32.tf32.tf32.f32 "
        "{%0,%1,%2,%3}, {%4,%5,%6,%7}, {%8,%9}, {%0,%1,%2,%3};\n"
        : "+f"(d[0]), "+f"(d[1]), "+f"(d[2]), "+f"(d[3])
        : "r"(a0), "r"(a1), "r"(a2), "r"(a3), "r"(b0), "r"(b1));
}

template<int EPI>
__global__ void __launch_bounds__(256) gemm_tf32(const float* __restrict__ A,
                                                 const float* __restrict__ Bw,
                                                 const float* __restrict__ bias,
                                                 const float* __restrict__ res,
                                                 float* __restrict__ C,
                                                 int M, int N, int K) {
    __shared__ float As[BM * SPITCH];
    __shared__ float Bs[BN * SPITCH];

    int tid = threadIdx.x;
    int m0 = blockIdx.y * BM;
    int n0 = blockIdx.x * BN;
    int warp = tid >> 5, lane = tid & 31;
    int wm = (warp & 1) * 64;       // warp M offset within block
    int wn = (warp >> 1) * 32;      // warp N offset within block
    int r4 = lane >> 2, cc = lane & 3;

    float acc[4][4][4];
    #pragma unroll
    for (int i = 0; i < 4; ++i)
        #pragma unroll
        for (int j = 0; j < 4; ++j)
            #pragma unroll
            for (int k = 0; k < 4; ++k) acc[i][j][k] = 0.f;

    int ldRow = tid >> 2;          // 0..63
    int ldK   = (tid & 3) * 4;     // 0,4,8,12
    const float* Ap = A  + (size_t)(m0 + ldRow) * K + ldK;
    const float* Bp = Bw + (size_t)(n0 + ldRow) * K + ldK;
    size_t half = (size_t)64 * K;

    float4 ra0 = *(const float4*)(Ap);
    float4 ra1 = *(const float4*)(Ap + half);
    float4 rb0 = *(const float4*)(Bp);
    float4 rb1 = *(const float4*)(Bp + half);

    int ntiles = K / BK;
    for (int t = 0; t < ntiles; ++t) {
        __syncthreads();
        *(float4*)&As[ldRow * SPITCH + ldK]        = tf32r4(ra0);
        *(float4*)&As[(ldRow + 64) * SPITCH + ldK] = tf32r4(ra1);
        *(float4*)&Bs[ldRow * SPITCH + ldK]        = tf32r4(rb0);
        *(float4*)&Bs[(ldRow + 64) * SPITCH + ldK] = tf32r4(rb1);
        __syncthreads();

        if (t + 1 < ntiles) {
            int off = (t + 1) * BK;
            ra0 = *(const float4*)(Ap + off);
            ra1 = *(const float4*)(Ap + half + off);
            rb0 = *(const float4*)(Bp + off);
            rb1 = *(const float4*)(Bp + half + off);
        }

        #pragma unroll
        for (int ks = 0; ks < 2; ++ks) {
            int k0 = ks * 8;
            uint32_t af[4][4], bf[4][2];
            #pragma unroll
            for (int mt = 0; mt < 4; ++mt) {
                int rb = wm + mt * 16;
                af[mt][0] = __float_as_uint(As[(rb + r4)     * SPITCH + k0 + cc]);
                af[mt][1] = __float_as_uint(As[(rb + r4 + 8) * SPITCH + k0 + cc]);
                af[mt][2] = __float_as_uint(As[(rb + r4)     * SPITCH + k0 + cc + 4]);
                af[mt][3] = __float_as_uint(As[(rb + r4 + 8) * SPITCH + k0 + cc + 4]);
            }
            #pragma unroll
            for (int nt = 0; nt < 4; ++nt) {
                int nb = wn + nt * 8;
                bf[nt][0] = __float_as_uint(Bs[(nb + r4) * SPITCH + k0 + cc]);
                bf[nt][1] = __float_as_uint(Bs[(nb + r4) * SPITCH + k0 + cc + 4]);
            }
            #pragma unroll
            for (int mt = 0; mt < 4; ++mt)
                #pragma unroll
                for (int nt = 0; nt < 4; ++nt)
                    mma_tf32(acc[mt][nt], af[mt][0], af[mt][1], af[mt][2], af[mt][3],
                             bf[nt][0], bf[nt][1]);
        }
    }

    // epilogue: c0,c1 at (row, col), (row, col+1); c2,c3 at (row+8, ...)
    #pragma unroll
    for (int mt = 0; mt < 4; ++mt) {
        int row0 = m0 + wm + mt * 16 + r4;
        #pragma unroll
        for (int nt = 0; nt < 4; ++nt) {
            int col = n0 + wn + nt * 8 + cc * 2;
            float b0v = bias[col], b1v = bias[col + 1];

            float v0 = acc[mt][nt][0] + b0v;
            float v1 = acc[mt][nt][1] + b1v;
            float v2 = acc[mt][nt][2] + b0v;
            float v3 = acc[mt][nt][3] + b1v;
            if (EPI == 1) {
                v0 = gelu_exact(v0); v1 = gelu_exact(v1);
                v2 = gelu_exact(v2); v3 = gelu_exact(v3);
            }
            if (EPI == 2) {
                float2 r0 = *(const float2*)&res[(size_t)row0 * N + col];
                float2 r1 = *(const float2*)&res[(size_t)(row0 + 8) * N + col];
                v0 += r0.x; v1 += r0.y; v2 += r1.x; v3 += r1.y;
            }
            float2 o0 = make_float2(v0, v1);
            float2 o1 = make_float2(v2, v3);
            *(float2*)&C[(size_t)row0 * N + col]       = o0;
            *(float2*)&C[(size_t)(row0 + 8) * N + col] = o1;
        }
    }
}

// ---------------- Flash attention (fp32 SIMT) ----------------
#define APITCH 68

__global__ void __launch_bounds__(256) attn_kernel(const float* __restrict__ qkv,
                                                   float* __restrict__ ctx) {
    extern __shared__ float sm[];
    float* Qs = sm;
    float* Ks = Qs + 64 * APITCH;
    float* Vs = Ks + 64 * APITCH;
    float* Ps = Vs + 64 * APITCH;

    int t = threadIdx.x;
    int b = blockIdx.z, h = blockIdx.y;
    int s0 = blockIdx.x * 64;
    int r = t >> 2, q = t & 3;

    const float* qbase = qkv + ((size_t)(b * 1024 + s0) * 3072) + h * HEAD_D;
    const float* kbase = qkv + ((size_t)b * 1024 * 3072) + 1024 + h * HEAD_D;
    const float* vbase = qkv + ((size_t)b * 1024 * 3072) + 2048 + h * HEAD_D;

    #pragma unroll
    for (int p = 0; p < 4; ++p) {
        int j = t + 256 * p;
        int row = j >> 4, c4 = j & 15;
        *(float4*)&Qs[row * APITCH + c4 * 4] =
            *(const float4*)(qbase + (size_t)row * 3072 + c4 * 4);
    }

    float mrun = -1e30f, l = 0.f;
    float o[16];
    #pragma unroll
    for (int i = 0; i < 16; ++i) o[i] = 0.f;
    const float scale = 0.125f;

    for (int j0 = 0; j0 < 1024; j0 += 64) {
        __syncthreads();
        #pragma unroll
        for (int p = 0; p < 4; ++p) {
            int j = t + 256 * p;
            int row = j >> 4, c4 = j & 15;
            *(float4*)&Ks[row * APITCH + c4 * 4] =
                *(const float4*)(kbase + (size_t)(j0 + row) * 3072 + c4 * 4);
            *(float4*)&Vs[row * APITCH + c4 * 4] =
                *(const float4*)(vbase + (size_t)(j0 + row) * 3072 + c4 * 4);
        }
        __syncthreads();

        float s[16];
        #pragma unroll
        for (int c = 0; c < 16; ++c) s[c] = 0.f;
        #pragma unroll
        for (int d4 = 0; d4 < 16; ++d4) {
            float4 qv = *(const float4*)&Qs[r * APITCH + d4 * 4];
            #pragma unroll
            for (int c = 0; c < 16; ++c) {
                float4 kv = *(const float4*)&Ks[(c * 4 + q) * APITCH + d4 * 4];
                s[c] += qv.x*kv.x + qv.y*kv.y + qv.z*kv.z + qv.w*kv.w;
            }
        }

        float mloc = -1e30f;
        #pragma unroll
        for (int c = 0; c < 16; ++c) { s[c] *= scale; mloc = fmaxf(mloc, s[c]); }
        mloc = fmaxf(mloc, __shfl_xor_sync(0xffffffffu, mloc, 1));
        mloc = fmaxf(mloc, __shfl_xor_sync(0xffffffffu, mloc, 2));
        float mnew = fmaxf(mrun, mloc);
        float alpha = __expf(mrun - mnew);

        float psum = 0.f;
        #pragma unroll
        for (int c = 0; c < 16; ++c) {
            float pv = __expf(s[c] - mnew);
            psum += pv;
            Ps[r * APITCH + c * 4 + q] = pv;
        }
        psum += __shfl_xor_sync(0xffffffffu, psum, 1);
        psum += __shfl_xor_sync(0xffffffffu, psum, 2);
        l = l * alpha + psum;
        mrun = mnew;
        #pragma unroll
        for (int i = 0; i < 16; ++i) o[i] *= alpha;
        __syncthreads();

        #pragma unroll 4
        for (int c2 = 0; c2 < 64; ++c2) {
            float pv = Ps[r * APITCH + c2];
            #pragma unroll
            for (int i4 = 0; i4 < 4; ++i4) {
                float4 vv = *(const float4*)&Vs[c2 * APITCH + q * 16 + i4 * 4];
                o[i4*4+0] = fmaf(pv, vv.x, o[i4*4+0]);
                o[i4*4+1] = fmaf(pv, vv.y, o[i4*4+1]);
                o[i4*4+2] = fmaf(pv, vv.z, o[i4*4+2]);
                o[i4*4+3] = fmaf(pv, vv.w, o[i4*4+3]);
            }
        }
    }

    float inv = 1.0f / l;
    float* outp = ctx + ((size_t)(b * 1024 + s0 + r) * D_MODEL) + h * HEAD_D + q * 16;
    #pragma unroll
    for (int i4 = 0; i4 < 4; ++i4) {
        float4 w;
        w.x = o[i4*4+0] * inv; w.y = o[i4*4+1] * inv;
        w.z = o[i4*4+2] * inv; w.w = o[i4*4+3] * inv;
        *(float4*)(outp + i4 * 4) = w;
    }
}

// ---------------- launch ----------------
extern "C" void kernel_launch(void* const* d_in, const int* in_sizes, int n_in,
                              void* d_out, int out_size) {
    const float* x      = (const float*)d_in[0];
    const float* qkv_w  = (const float*)d_in[1];
    const float* qkv_b  = (const float*)d_in[2];
    const float* proj_w = (const float*)d_in[3];
    const float* proj_b = (const float*)d_in[4];
    const float* fc1_w  = (const float*)d_in[5];
    const float* fc1_b  = (const float*)d_in[6];
    const float* fc2_w  = (const float*)d_in[7];
    const float* fc2_b  = (const float*)d_in[8];
    const float* ln1_g  = (const float*)d_in[9];
    const float* ln1_b  = (const float*)d_in[10];
    const float* ln2_g  = (const float*)d_in[11];
    const float* ln2_b  = (const float*)d_in[12];
    float* out = (float*)d_out;

    float *h, *qkv, *ctx, *x2, *ff;
    cudaGetSymbolAddress((void**)&h,   g_h);
    cudaGetSymbolAddress((void**)&qkv, g_qkv);
    cudaGetSymbolAddress((void**)&ctx, g_ctx);
    cudaGetSymbolAddress((void**)&x2,  g_x2);
    cudaGetSymbolAddress((void**)&ff,  g_ff);

    int attn_smem = 4 * 64 * APITCH * (int)sizeof(float);
    cudaFuncSetAttribute(attn_kernel, cudaFuncAttributeMaxDynamicSharedMemorySize,
                         attn_smem);

    // 1. LN1
    ln_kernel<<<N_TOK, 256>>>(x, ln1_g, ln1_b, h);
    // 2. QKV = h @ qkv_w^T + qkv_b
    gemm_tf32<0><<<dim3(3 * D_MODEL / BN, N_TOK / BM), 256>>>(
        h, qkv_w, qkv_b, nullptr, qkv, N_TOK, 3 * D_MODEL, D_MODEL);
    // 3. attention
    attn_kernel<<<dim3(1024 / 64, N_HEAD, 8), 256, attn_smem>>>(qkv, ctx);
    // 4. x2 = x + ctx @ proj_w^T + proj_b
    gemm_tf32<2><<<dim3(D_MODEL / BN, N_TOK / BM), 256>>>(
        ctx, proj_w, proj_b, x, x2, N_TOK, D_MODEL, D_MODEL);
    // 5. LN2
    ln_kernel<<<N_TOK, 256>>>(x2, ln2_g, ln2_b, h);
    // 6. ff = gelu(h @ fc1_w^T + fc1_b)
    gemm_tf32<1><<<dim3(FF_DIM / BN, N_TOK / BM), 256>>>(
        h, fc1_w, fc1_b, nullptr, ff, N_TOK, FF_DIM, D_MODEL);
    // 7. out = x2 + ff @ fc2_w^T + fc2_b
    gemm_tf32<2><<<dim3(D_MODEL / BN, N_TOK / BM), 256>>>(
        ff, fc2_w, fc2_b, x2, out, N_TOK, D_MODEL, FF_DIM);
}

// round 3
// speedup vs baseline: 3.6354x; 2.1686x over previous
#include <cuda_runtime.h>
#include <math.h>
#include <stdint.h>

#define D_MODEL 1024
#define N_TOK   8192
#define FF_DIM  4096
#define N_HEAD  16
#define HEAD_D  64

__device__ float g_h  [N_TOK * D_MODEL];
__device__ float g_qkv[N_TOK * 3 * D_MODEL];
__device__ float g_ctx[N_TOK * D_MODEL];
__device__ float g_x2 [N_TOK * D_MODEL];
__device__ float g_ff [N_TOK * FF_DIM];

// ---------------- helpers ----------------
__device__ __forceinline__ float gelu_exact(float v) {
    return 0.5f * v * (1.0f + erff(v * 0.70710678118654752440f));
}
__device__ __forceinline__ float tf32r(float x) {
    uint32_t u;
    asm("cvt.rna.tf32.f32 %0, %1;" : "=r"(u) : "f"(x));
    return __uint_as_float(u);
}
__device__ __forceinline__ float4 tf32r4(float4 v) {
    v.x = tf32r(v.x); v.y = tf32r(v.y); v.z = tf32r(v.z); v.w = tf32r(v.w);
    return v;
}
__device__ __forceinline__ void mma_tf32(float d[4], uint32_t a0, uint32_t a1,
                                         uint32_t a2, uint32_t a3,
                                         uint32_t b0, uint32_t b1) {
    asm volatile(
        "mma.sync.aligned.m16n8k8.row.col.f32.tf32.tf32.f32 "
        "{%0,%1,%2,%3}, {%4,%5,%6,%7}, {%8,%9}, {%0,%1,%2,%3};\n"
        : "+f"(d[0]), "+f"(d[1]), "+f"(d[2]), "+f"(d[3])
        : "r"(a0), "r"(a1), "r"(a2), "r"(a3), "r"(b0), "r"(b1));
}

// ---------------- LayerNorm ----------------
__global__ void __launch_bounds__(256) ln_kernel(const float* __restrict__ x,
                                                 const float* __restrict__ g,
                                                 const float* __restrict__ b,
                                                 float* __restrict__ out) {
    int row = blockIdx.x;
    int t = threadIdx.x;
    const float* xr = x + (size_t)row * D_MODEL;
    float4 xv = ((const float4*)xr)[t];

    float s  = xv.x + xv.y + xv.z + xv.w;
    float sq = xv.x*xv.x + xv.y*xv.y + xv.z*xv.z + xv.w*xv.w;
    #pragma unroll
    for (int o = 16; o > 0; o >>= 1) {
        s  += __shfl_xor_sync(0xffffffffu, s,  o);
        sq += __shfl_xor_sync(0xffffffffu, sq, o);
    }
    __shared__ float red[2][8];
    int wid = t >> 5, lane = t & 31;
    if (lane == 0) { red[0][wid] = s; red[1][wid] = sq; }
    __syncthreads();
    float tot = 0.f, tot2 = 0.f;
    #pragma unroll
    for (int w = 0; w < 8; ++w) { tot += red[0][w]; tot2 += red[1][w]; }
    float mu = tot * (1.0f / D_MODEL);
    float var = tot2 * (1.0f / D_MODEL) - mu * mu;
    float rstd = rsqrtf(var + 1e-6f);

    float4 gv = ((const float4*)g)[t];
    float4 bv = ((const float4*)b)[t];
    float4 ov;
    ov.x = (xv.x - mu) * rstd * gv.x + bv.x;
    ov.y = (xv.y - mu) * rstd * gv.y + bv.y;
    ov.z = (xv.z - mu) * rstd * gv.z + bv.z;
    ov.w = (xv.w - mu) * rstd * gv.w + bv.w;
    ((float4*)(out + (size_t)row * D_MODEL))[t] = ov;
}

// ---------------- TF32 GEMM, double-buffered ----------------
#define BM 128
#define BN 128
#define BK 16
#define SPITCH 20

template<int EPI>
__global__ void __launch_bounds__(256) gemm_tf32(const float* __restrict__ A,
                                                 const float* __restrict__ Bw,
                                                 const float* __restrict__ bias,
                                                 const float* __restrict__ res,
                                                 float* __restrict__ C,
                                                 int M, int N, int K) {
    __shared__ float As[2][BM * SPITCH];
    __shared__ float Bs[2][BN * SPITCH];

    int tid = threadIdx.x;
    int m0 = blockIdx.y * BM;
    int n0 = blockIdx.x * BN;
    int warp = tid >> 5, lane = tid & 31;
    int wm = (warp & 1) * 64;
    int wn = (warp >> 1) * 32;
    int r4 = lane >> 2, cc = lane & 3;

    float acc[4][4][4];
    #pragma unroll
    for (int i = 0; i < 4; ++i)
        #pragma unroll
        for (int j = 0; j < 4; ++j)
            #pragma unroll
            for (int k = 0; k < 4; ++k) acc[i][j][k] = 0.f;

    int ldRow = tid >> 2;
    int ldK   = (tid & 3) * 4;
    const float* Ap = A  + (size_t)(m0 + ldRow) * K + ldK;
    const float* Bp = Bw + (size_t)(n0 + ldRow) * K + ldK;
    size_t half = (size_t)64 * K;

    float4 ra0 = *(const float4*)(Ap);
    float4 ra1 = *(const float4*)(Ap + half);
    float4 rb0 = *(const float4*)(Bp);
    float4 rb1 = *(const float4*)(Bp + half);
    *(float4*)&As[0][ldRow * SPITCH + ldK]        = tf32r4(ra0);
    *(float4*)&As[0][(ldRow + 64) * SPITCH + ldK] = tf32r4(ra1);
    *(float4*)&Bs[0][ldRow * SPITCH + ldK]        = tf32r4(rb0);
    *(float4*)&Bs[0][(ldRow + 64) * SPITCH + ldK] = tf32r4(rb1);
    __syncthreads();

    int ntiles = K / BK;
    for (int t = 0; t < ntiles; ++t) {
        int cur = t & 1;
        if (t + 1 < ntiles) {
            int off = (t + 1) * BK;
            ra0 = *(const float4*)(Ap + off);
            ra1 = *(const float4*)(Ap + half + off);
            rb0 = *(const float4*)(Bp + off);
            rb1 = *(const float4*)(Bp + half + off);
        }

        #pragma unroll
        for (int ks = 0; ks < 2; ++ks) {
            int k0 = ks * 8;
            uint32_t af[4][4], bf[4][2];
            #pragma unroll
            for (int mt = 0; mt < 4; ++mt) {
                int rb = wm + mt * 16;
                af[mt][0] = __float_as_uint(As[cur][(rb + r4)     * SPITCH + k0 + cc]);
                af[mt][1] = __float_as_uint(As[cur][(rb + r4 + 8) * SPITCH + k0 + cc]);
                af[mt][2] = __float_as_uint(As[cur][(rb + r4)     * SPITCH + k0 + cc + 4]);
                af[mt][3] = __float_as_uint(As[cur][(rb + r4 + 8) * SPITCH + k0 + cc + 4]);
            }
            #pragma unroll
            for (int nt = 0; nt < 4; ++nt) {
                int nb = wn + nt * 8;
                bf[nt][0] = __float_as_uint(Bs[cur][(nb + r4) * SPITCH + k0 + cc]);
                bf[nt][1] = __float_as_uint(Bs[cur][(nb + r4) * SPITCH + k0 + cc + 4]);
            }
            #pragma unroll
            for (int mt = 0; mt < 4; ++mt)
                #pragma unroll
                for (int nt = 0; nt < 4; ++nt)
                    mma_tf32(acc[mt][nt], af[mt][0], af[mt][1], af[mt][2], af[mt][3],
                             bf[nt][0], bf[nt][1]);
        }

        if (t + 1 < ntiles) {
            int nxt = (t + 1) & 1;
            *(float4*)&As[nxt][ldRow * SPITCH + ldK]        = tf32r4(ra0);
            *(float4*)&As[nxt][(ldRow + 64) * SPITCH + ldK] = tf32r4(ra1);
            *(float4*)&Bs[nxt][ldRow * SPITCH + ldK]        = tf32r4(rb0);
            *(float4*)&Bs[nxt][(ldRow + 64) * SPITCH + ldK] = tf32r4(rb1);
            __syncthreads();
        }
    }

    #pragma unroll
    for (int mt = 0; mt < 4; ++mt) {
        int row0 = m0 + wm + mt * 16 + r4;
        #pragma unroll
        for (int nt = 0; nt < 4; ++nt) {
            int col = n0 + wn + nt * 8 + cc * 2;
            float b0v = bias[col], b1v = bias[col + 1];
            float v0 = acc[mt][nt][0] + b0v;
            float v1 = acc[mt][nt][1] + b1v;
            float v2 = acc[mt][nt][2] + b0v;
            float v3 = acc[mt][nt][3] + b1v;
            if (EPI == 1) {
                v0 = gelu_exact(v0); v1 = gelu_exact(v1);
                v2 = gelu_exact(v2); v3 = gelu_exact(v3);
            }
            if (EPI == 2) {
                float2 r0 = *(const float2*)&res[(size_t)row0 * N + col];
                float2 r1 = *(const float2*)&res[(size_t)(row0 + 8) * N + col];
                v0 += r0.x; v1 += r0.y; v2 += r1.x; v3 += r1.y;
            }
            *(float2*)&C[(size_t)row0 * N + col]       = make_float2(v0, v1);
            *(float2*)&C[(size_t)(row0 + 8) * N + col] = make_float2(v2, v3);
        }
    }
}

// ---------------- Tensor-core flash attention ----------------
// 4 warps/CTA; warp w owns q-rows [w*16, w*16+16). 64 q-rows per CTA.
#define APITCH 68

__global__ void __launch_bounds__(128) attn_tc(const float* __restrict__ qkv,
                                               float* __restrict__ ctx) {
    extern __shared__ float sm[];
    float* Qs = sm;                    // 64 x APITCH (tf32)
    float* Ks = Qs + 64 * APITCH;      // 64 x APITCH (tf32)
    float* Vs = Ks + 64 * APITCH;      // 64 x APITCH (tf32)
    float* Ps = Vs + 64 * APITCH;      // 64 x APITCH (tf32 P values)

    int t = threadIdx.x;
    int warp = t >> 5, lane = t & 31;
    int r4 = lane >> 2, cc = lane & 3;
    int b = blockIdx.z, h = blockIdx.y;
    int s0 = blockIdx.x * 64;
    int wq = warp * 16;

    const float* qbase = qkv + (size_t)(b * 1024 + s0) * 3072 + h * HEAD_D;
    const float* kbase = qkv + (size_t)b * 1024 * 3072 + 1024 + h * HEAD_D;
    const float* vbase = qkv + (size_t)b * 1024 * 3072 + 2048 + h * HEAD_D;

    #pragma unroll
    for (int p = 0; p < 8; ++p) {
        int j = t + 128 * p;           // 0..1023 float4 slots
        int row = j >> 4, c4 = j & 15;
        *(float4*)&Qs[row * APITCH + c4 * 4] =
            tf32r4(*(const float4*)(qbase + (size_t)row * 3072 + c4 * 4));
    }

    float mr_lo = -1e30f, mr_hi = -1e30f, l_lo = 0.f, l_hi = 0.f;
    float oacc[8][4];
    #pragma unroll
    for (int i = 0; i < 8; ++i)
        #pragma unroll
        for (int j = 0; j < 4; ++j) oacc[i][j] = 0.f;
    const float scale = 0.125f;

    for (int j0 = 0; j0 < 1024; j0 += 64) {
        __syncthreads();
        #pragma unroll
        for (int p = 0; p < 8; ++p) {
            int j = t + 128 * p;
            int row = j >> 4, c4 = j & 15;
            *(float4*)&Ks[row * APITCH + c4 * 4] =
                tf32r4(*(const float4*)(kbase + (size_t)(j0 + row) * 3072 + c4 * 4));
            *(float4*)&Vs[row * APITCH + c4 * 4] =
                tf32r4(*(const float4*)(vbase + (size_t)(j0 + row) * 3072 + c4 * 4));
        }
        __syncthreads();

        // ---- S = Q K^T  (16 x 64 per warp) ----
        float sacc[8][4];
        #pragma unroll
        for (int i = 0; i < 8; ++i)
            #pragma unroll
            for (int j = 0; j < 4; ++j) sacc[i][j] = 0.f;

        #pragma unroll
        for (int kk = 0; kk < 8; ++kk) {
            int k0 = kk * 8;
            uint32_t a0 = __float_as_uint(Qs[(wq + r4)     * APITCH + k0 + cc]);
            uint32_t a1 = __float_as_uint(Qs[(wq + r4 + 8) * APITCH + k0 + cc]);
            uint32_t a2 = __float_as_uint(Qs[(wq + r4)     * APITCH + k0 + cc + 4]);
            uint32_t a3 = __float_as_uint(Qs[(wq + r4 + 8) * APITCH + k0 + cc + 4]);
            #pragma unroll
            for (int nt = 0; nt < 8; ++nt) {
                uint32_t b0 = __float_as_uint(Ks[(nt * 8 + r4) * APITCH + k0 + cc]);
                uint32_t b1 = __float_as_uint(Ks[(nt * 8 + r4) * APITCH + k0 + cc + 4]);
                mma_tf32(sacc[nt], a0, a1, a2, a3, b0, b1);
            }
        }

        // ---- online softmax ----
        float mlo = -1e30f, mhi = -1e30f;
        #pragma unroll
        for (int nt = 0; nt < 8; ++nt) {
            sacc[nt][0] *= scale; sacc[nt][1] *= scale;
            sacc[nt][2] *= scale; sacc[nt][3] *= scale;
            mlo = fmaxf(mlo, fmaxf(sacc[nt][0], sacc[nt][1]));
            mhi = fmaxf(mhi, fmaxf(sacc[nt][2], sacc[nt][3]));
        }
        mlo = fmaxf(mlo, __shfl_xor_sync(0xffffffffu, mlo, 1));
        mlo = fmaxf(mlo, __shfl_xor_sync(0xffffffffu, mlo, 2));
        mhi = fmaxf(mhi, __shfl_xor_sync(0xffffffffu, mhi, 1));
        mhi = fmaxf(mhi, __shfl_xor_sync(0xffffffffu, mhi, 2));
        float mn_lo = fmaxf(mr_lo, mlo), mn_hi = fmaxf(mr_hi, mhi);
        float al_lo = __expf(mr_lo - mn_lo), al_hi = __expf(mr_hi - mn_hi);

        float ps_lo = 0.f, ps_hi = 0.f;
        #pragma unroll
        for (int nt = 0; nt < 8; ++nt) {
            float p0 = __expf(sacc[nt][0] - mn_lo);
            float p1 = __expf(sacc[nt][1] - mn_lo);
            float p2 = __expf(sacc[nt][2] - mn_hi);
            float p3 = __expf(sacc[nt][3] - mn_hi);
            ps_lo += p0 + p1; ps_hi += p2 + p3;
            int colb = nt * 8 + cc * 2;
            Ps[(wq + r4)     * APITCH + colb]     = tf32r(p0);
            Ps[(wq + r4)     * APITCH + colb + 1] = tf32r(p1);
            Ps[(wq + r4 + 8) * APITCH + colb]     = tf32r(p2);
            Ps[(wq + r4 + 8) * APITCH + colb + 1] = tf32r(p3);
        }
        ps_lo += __shfl_xor_sync(0xffffffffu, ps_lo, 1);
        ps_lo += __shfl_xor_sync(0xffffffffu, ps_lo, 2);
        ps_hi += __shfl_xor_sync(0xffffffffu, ps_hi, 1);
        ps_hi += __shfl_xor_sync(0xffffffffu, ps_hi, 2);
        l_lo = l_lo * al_lo + ps_lo;
        l_hi = l_hi * al_hi + ps_hi;
        mr_lo = mn_lo; mr_hi = mn_hi;
        #pragma unroll
        for (int nt = 0; nt < 8; ++nt) {
            oacc[nt][0] *= al_lo; oacc[nt][1] *= al_lo;
            oacc[nt][2] *= al_hi; oacc[nt][3] *= al_hi;
        }
        __syncwarp();

        // ---- O += P V  (16 x 64 per warp) ----
        #pragma unroll
        for (int kk = 0; kk < 8; ++kk) {
            int k0 = kk * 8;
            uint32_t a0 = __float_as_uint(Ps[(wq + r4)     * APITCH + k0 + cc]);
            uint32_t a1 = __float_as_uint(Ps[(wq + r4 + 8) * APITCH + k0 + cc]);
            uint32_t a2 = __float_as_uint(Ps[(wq + r4)     * APITCH + k0 + cc + 4]);
            uint32_t a3 = __float_as_uint(Ps[(wq + r4 + 8) * APITCH + k0 + cc + 4]);
            #pragma unroll
            for (int nt = 0; nt < 8; ++nt) {
                uint32_t b0 = __float_as_uint(Vs[(k0 + cc)     * APITCH + nt * 8 + r4]);
                uint32_t b1 = __float_as_uint(Vs[(k0 + cc + 4) * APITCH + nt * 8 + r4]);
                mma_tf32(oacc[nt], a0, a1, a2, a3, b0, b1);
            }
        }
    }

    float il_lo = 1.f / l_lo, il_hi = 1.f / l_hi;
    int row_lo = b * 1024 + s0 + wq + r4;
    #pragma unroll
    for (int nt = 0; nt < 8; ++nt) {
        int col = h * HEAD_D + nt * 8 + cc * 2;
        *(float2*)&ctx[(size_t)row_lo * D_MODEL + col] =
            make_float2(oacc[nt][0] * il_lo, oacc[nt][1] * il_lo);
        *(float2*)&ctx[(size_t)(row_lo + 8) * D_MODEL + col] =
            make_float2(oacc[nt][2] * il_hi, oacc[nt][3] * il_hi);
    }
}

// ---------------- launch ----------------
extern "C" void kernel_launch(void* const* d_in, const int* in_sizes, int n_in,
                              void* d_out, int out_size) {
    const float* x      = (const float*)d_in[0];
    const float* qkv_w  = (const float*)d_in[1];
    const float* qkv_b  = (const float*)d_in[2];
    const float* proj_w = (const float*)d_in[3];
    const float* proj_b = (const float*)d_in[4];
    const float* fc1_w  = (const float*)d_in[5];
    const float* fc1_b  = (const float*)d_in[6];
    const float* fc2_w  = (const float*)d_in[7];
    const float* fc2_b  = (const float*)d_in[8];
    const float* ln1_g  = (const float*)d_in[9];
    const float* ln1_b  = (const float*)d_in[10];
    const float* ln2_g  = (const float*)d_in[11];
    const float* ln2_b  = (const float*)d_in[12];
    float* out = (float*)d_out;

    float *h, *qkv, *ctx, *x2, *ff;
    cudaGetSymbolAddress((void**)&h,   g_h);
    cudaGetSymbolAddress((void**)&qkv, g_qkv);
    cudaGetSymbolAddress((void**)&ctx, g_ctx);
    cudaGetSymbolAddress((void**)&x2,  g_x2);
    cudaGetSymbolAddress((void**)&ff,  g_ff);

    int attn_smem = 4 * 64 * APITCH * (int)sizeof(float);   // 69632 B
    cudaFuncSetAttribute(attn_tc, cudaFuncAttributeMaxDynamicSharedMemorySize,
                         attn_smem);

    ln_kernel<<<N_TOK, 256>>>(x, ln1_g, ln1_b, h);
    gemm_tf32<0><<<dim3(3 * D_MODEL / BN, N_TOK / BM), 256>>>(
        h, qkv_w, qkv_b, nullptr, qkv, N_TOK, 3 * D_MODEL, D_MODEL);
    attn_tc<<<dim3(1024 / 64, N_HEAD, 8), 128, attn_smem>>>(qkv, ctx);
    gemm_tf32<2><<<dim3(D_MODEL / BN, N_TOK / BM), 256>>>(
        ctx, proj_w, proj_b, x, x2, N_TOK, D_MODEL, D_MODEL);
    ln_kernel<<<N_TOK, 256>>>(x2, ln2_g, ln2_b, h);
    gemm_tf32<1><<<dim3(FF_DIM / BN, N_TOK / BM), 256>>>(
        h, fc1_w, fc1_b, nullptr, ff, N_TOK, FF_DIM, D_MODEL);
    gemm_tf32<2><<<dim3(D_MODEL / BN, N_TOK / BM), 256>>>(
        ff, fc2_w, fc2_b, x2, out, N_TOK, D_MODEL, FF_DIM);
}

// round 4
// speedup vs baseline: 4.6570x; 1.2810x over previous
#include <cuda_runtime.h>
#include <math.h>
#include <stdint.h>

#define D_MODEL 1024
#define N_TOK   8192
#define FF_DIM  4096
#define N_HEAD  16
#define HEAD_D  64

__device__ float g_h  [N_TOK * D_MODEL];
__device__ float g_qkv[N_TOK * 3 * D_MODEL];
__device__ float g_ctx[N_TOK * D_MODEL];
__device__ float g_x2 [N_TOK * D_MODEL];
__device__ float g_ff [N_TOK * FF_DIM];
// tf32-pre-rounded weights
__device__ float g_wq[3 * D_MODEL * D_MODEL];
__device__ float g_wp[D_MODEL * D_MODEL];
__device__ float g_w1[FF_DIM * D_MODEL];
__device__ float g_w2[D_MODEL * FF_DIM];

// ---------------- helpers ----------------
__device__ __forceinline__ float gelu_exact(float v) {
    return 0.5f * v * (1.0f + erff(v * 0.70710678118654752440f));
}
__device__ __forceinline__ float tf32r(float x) {
    uint32_t u;
    asm("cvt.rna.tf32.f32 %0, %1;" : "=r"(u) : "f"(x));
    return __uint_as_float(u);
}
__device__ __forceinline__ float4 tf32r4(float4 v) {
    v.x = tf32r(v.x); v.y = tf32r(v.y); v.z = tf32r(v.z); v.w = tf32r(v.w);
    return v;
}
__device__ __forceinline__ void mma_tf32(float d[4], uint32_t a0, uint32_t a1,
                                         uint32_t a2, uint32_t a3,
                                         uint32_t b0, uint32_t b1) {
    asm volatile(
        "mma.sync.aligned.m16n8k8.row.col.f32.tf32.tf32.f32 "
        "{%0,%1,%2,%3}, {%4,%5,%6,%7}, {%8,%9}, {%0,%1,%2,%3};\n"
        : "+f"(d[0]), "+f"(d[1]), "+f"(d[2]), "+f"(d[3])
        : "r"(a0), "r"(a1), "r"(a2), "r"(a3), "r"(b0), "r"(b1));
}
__device__ __forceinline__ void ldsm4(uint32_t& r0, uint32_t& r1, uint32_t& r2,
                                      uint32_t& r3, uint32_t addr) {
    asm volatile("ldmatrix.sync.aligned.m8n8.x4.shared.b16 {%0,%1,%2,%3}, [%4];"
                 : "=r"(r0), "=r"(r1), "=r"(r2), "=r"(r3) : "r"(addr));
}
__device__ __forceinline__ void cp16(uint32_t smem, const void* g) {
    asm volatile("cp.async.cg.shared.global [%0], [%1], 16;" :: "r"(smem), "l"(g));
}
__device__ __forceinline__ void cp_commit() {
    asm volatile("cp.async.commit_group;");
}
__device__ __forceinline__ void cp_wait2() {
    asm volatile("cp.async.wait_group 2;");
}

// ---------------- weight pre-round ----------------
__global__ void __launch_bounds__(256) round_w(const float* __restrict__ in,
                                               float* __restrict__ out, int n4) {
    int i = blockIdx.x * 256 + threadIdx.x;
    if (i < n4) ((float4*)out)[i] = tf32r4(((const float4*)in)[i]);
}

// ---------------- LayerNorm (tf32-rounded output) ----------------
__global__ void __launch_bounds__(256) ln_kernel(const float* __restrict__ x,
                                                 const float* __restrict__ g,
                                                 const float* __restrict__ b,
                                                 float* __restrict__ out) {
    int row = blockIdx.x;
    int t = threadIdx.x;
    const float* xr = x + (size_t)row * D_MODEL;
    float4 xv = ((const float4*)xr)[t];

    float s  = xv.x + xv.y + xv.z + xv.w;
    float sq = xv.x*xv.x + xv.y*xv.y + xv.z*xv.z + xv.w*xv.w;
    #pragma unroll
    for (int o = 16; o > 0; o >>= 1) {
        s  += __shfl_xor_sync(0xffffffffu, s,  o);
        sq += __shfl_xor_sync(0xffffffffu, sq, o);
    }
    __shared__ float red[2][8];
    int wid = t >> 5, lane = t & 31;
    if (lane == 0) { red[0][wid] = s; red[1][wid] = sq; }
    __syncthreads();
    float tot = 0.f, tot2 = 0.f;
    #pragma unroll
    for (int w = 0; w < 8; ++w) { tot += red[0][w]; tot2 += red[1][w]; }
    float mu = tot * (1.0f / D_MODEL);
    float var = tot2 * (1.0f / D_MODEL) - mu * mu;
    float rstd = rsqrtf(var + 1e-6f);

    float4 gv = ((const float4*)g)[t];
    float4 bv = ((const float4*)b)[t];
    float4 ov;
    ov.x = (xv.x - mu) * rstd * gv.x + bv.x;
    ov.y = (xv.y - mu) * rstd * gv.y + bv.y;
    ov.z = (xv.z - mu) * rstd * gv.z + bv.z;
    ov.w = (xv.w - mu) * rstd * gv.w + bv.w;
    ((float4*)(out + (size_t)row * D_MODEL))[t] = tf32r4(ov);
}

// ---------------- TF32 GEMM: cp.async 4-stage + ldmatrix ----------------
// All A/B inputs must be pre-rounded to tf32.
#define BM 128
#define BN 128
#define BK 16
#define SPITCH 20
#define STAGES 4
#define STAGE_FLOATS (2 * BM * SPITCH)           // A then B, 5120 floats
#define STAGE_BYTES  (STAGE_FLOATS * 4)          // 20480
#define B_OFF_BYTES  (BM * SPITCH * 4)           // 10240

template<int EPI, int RND>
__global__ void __launch_bounds__(256, 2) gemm_cp(const float* __restrict__ A,
                                                  const float* __restrict__ Bw,
                                                  const float* __restrict__ bias,
                                                  const float* __restrict__ res,
                                                  float* __restrict__ C,
                                                  int M, int N, int K) {
    extern __shared__ float smem[];
    uint32_t smem_u = (uint32_t)__cvta_generic_to_shared(smem);

    int tid = threadIdx.x;
    int m0 = blockIdx.y * BM;
    int n0 = blockIdx.x * BN;
    int warp = tid >> 5, lane = tid & 31;
    int wm = (warp & 1) * 64;
    int wn = (warp >> 1) * 32;
    int r4 = lane >> 2, cc = lane & 3;

    float acc[4][4][4];
    #pragma unroll
    for (int i = 0; i < 4; ++i)
        #pragma unroll
        for (int j = 0; j < 4; ++j)
            #pragma unroll
            for (int k = 0; k < 4; ++k) acc[i][j][k] = 0.f;

    // cp.async mapping: thread -> (row = tid/4, quad = tid%4), rows row & row+64
    int ldRow = tid >> 2;
    int ldQ   = (tid & 3) * 4;
    const float* Ap = A  + (size_t)(m0 + ldRow) * K + ldQ;
    const float* Bp = Bw + (size_t)(n0 + ldRow) * K + ldQ;
    size_t half = (size_t)64 * K;
    uint32_t aoff0 = (ldRow * SPITCH + ldQ) * 4;
    uint32_t aoff1 = ((ldRow + 64) * SPITCH + ldQ) * 4;

    // ldmatrix lane addressing
    int aRow = wm + (lane & 15);
    int aColB = ((lane >> 4) << 2);                 // 0 or 4
    uint32_t aBase = smem_u + (uint32_t)((aRow * SPITCH + aColB) * 4);
    int bRow = wn + (lane & 7) + ((lane & 16) >> 1); // +8 for lanes>=16
    int bColB = ((lane & 8) >> 1);                   // 0 or 4
    uint32_t bBase = smem_u + B_OFF_BYTES + (uint32_t)((bRow * SPITCH + bColB) * 4);

    int ntiles = K / BK;

    // prologue: fill STAGES-1 stages
    #pragma unroll
    for (int s = 0; s < STAGES - 1; ++s) {
        uint32_t sb = smem_u + s * STAGE_BYTES;
        int off = s * BK;
        cp16(sb + aoff0, Ap + off);
        cp16(sb + aoff1, Ap + half + off);
        cp16(sb + B_OFF_BYTES + aoff0, Bp + off);
        cp16(sb + B_OFF_BYTES + aoff1, Bp + half + off);
        cp_commit();
    }

    for (int t = 0; t < ntiles; ++t) {
        cp_wait2();
        __syncthreads();

        int tp = t + STAGES - 1;
        if (tp < ntiles) {
            uint32_t sb = smem_u + (tp & (STAGES - 1)) * STAGE_BYTES;
            int off = tp * BK;
            cp16(sb + aoff0, Ap + off);
            cp16(sb + aoff1, Ap + half + off);
            cp16(sb + B_OFF_BYTES + aoff0, Bp + off);
            cp16(sb + B_OFF_BYTES + aoff1, Bp + half + off);
        }
        cp_commit();

        uint32_t stg = (t & (STAGES - 1)) * STAGE_BYTES;
        #pragma unroll
        for (int ks = 0; ks < 2; ++ks) {
            uint32_t kof = stg + ks * 32;           // 8 floats
            uint32_t af[4][4], bf[4][2];
            #pragma unroll
            for (int mt = 0; mt < 4; ++mt)
                ldsm4(af[mt][0], af[mt][1], af[mt][2], af[mt][3],
                      aBase + kof + mt * (16 * SPITCH * 4));
            #pragma unroll
            for (int np = 0; np < 2; ++np)
                ldsm4(bf[2*np][0], bf[2*np][1], bf[2*np+1][0], bf[2*np+1][1],
                      bBase + kof + np * (16 * SPITCH * 4));
            #pragma unroll
            for (int mt = 0; mt < 4; ++mt)
                #pragma unroll
                for (int nt = 0; nt < 4; ++nt)
                    mma_tf32(acc[mt][nt], af[mt][0], af[mt][1], af[mt][2], af[mt][3],
                             bf[nt][0], bf[nt][1]);
        }
    }

    #pragma unroll
    for (int mt = 0; mt < 4; ++mt) {
        int row0 = m0 + wm + mt * 16 + r4;
        #pragma unroll
        for (int nt = 0; nt < 4; ++nt) {
            int col = n0 + wn + nt * 8 + cc * 2;
            float b0v = bias[col], b1v = bias[col + 1];
            float v0 = acc[mt][nt][0] + b0v;
            float v1 = acc[mt][nt][1] + b1v;
            float v2 = acc[mt][nt][2] + b0v;
            float v3 = acc[mt][nt][3] + b1v;
            if (EPI == 1) {
                v0 = gelu_exact(v0); v1 = gelu_exact(v1);
                v2 = gelu_exact(v2); v3 = gelu_exact(v3);
            }
            if (EPI == 2) {
                float2 r0 = *(const float2*)&res[(size_t)row0 * N + col];
                float2 r1 = *(const float2*)&res[(size_t)(row0 + 8) * N + col];
                v0 += r0.x; v1 += r0.y; v2 += r1.x; v3 += r1.y;
            }
            if (RND) {
                v0 = tf32r(v0); v1 = tf32r(v1); v2 = tf32r(v2); v3 = tf32r(v3);
            }
            *(float2*)&C[(size_t)row0 * N + col]       = make_float2(v0, v1);
            *(float2*)&C[(size_t)(row0 + 8) * N + col] = make_float2(v2, v3);
        }
    }
}

// ---------------- Tensor-core flash attention ----------------
#define APITCH 68

__global__ void __launch_bounds__(128) attn_tc(const float* __restrict__ qkv,
                                               float* __restrict__ ctx) {
    extern __shared__ float sm[];
    float* Qs = sm;
    float* Ks = Qs + 64 * APITCH;
    float* Vs = Ks + 64 * APITCH;
    float* Ps = Vs + 64 * APITCH;

    int t = threadIdx.x;
    int warp = t >> 5, lane = t & 31;
    int r4 = lane >> 2, cc = lane & 3;
    int b = blockIdx.z, h = blockIdx.y;
    int s0 = blockIdx.x * 64;
    int wq = warp * 16;

    const float* qbase = qkv + (size_t)(b * 1024 + s0) * 3072 + h * HEAD_D;
    const float* kbase = qkv + (size_t)b * 1024 * 3072 + 1024 + h * HEAD_D;
    const float* vbase = qkv + (size_t)b * 1024 * 3072 + 2048 + h * HEAD_D;

    #pragma unroll
    for (int p = 0; p < 8; ++p) {
        int j = t + 128 * p;
        int row = j >> 4, c4 = j & 15;
        *(float4*)&Qs[row * APITCH + c4 * 4] =
            tf32r4(*(const float4*)(qbase + (size_t)row * 3072 + c4 * 4));
    }

    float mr_lo = -1e30f, mr_hi = -1e30f, l_lo = 0.f, l_hi = 0.f;
    float oacc[8][4];
    #pragma unroll
    for (int i = 0; i < 8; ++i)
        #pragma unroll
        for (int j = 0; j < 4; ++j) oacc[i][j] = 0.f;
    const float scale = 0.125f;

    for (int j0 = 0; j0 < 1024; j0 += 64) {
        __syncthreads();
        #pragma unroll
        for (int p = 0; p < 8; ++p) {
            int j = t + 128 * p;
            int row = j >> 4, c4 = j & 15;
            *(float4*)&Ks[row * APITCH + c4 * 4] =
                tf32r4(*(const float4*)(kbase + (size_t)(j0 + row) * 3072 + c4 * 4));
            *(float4*)&Vs[row * APITCH + c4 * 4] =
                tf32r4(*(const float4*)(vbase + (size_t)(j0 + row) * 3072 + c4 * 4));
        }
        __syncthreads();

        float sacc[8][4];
        #pragma unroll
        for (int i = 0; i < 8; ++i)
            #pragma unroll
            for (int j = 0; j < 4; ++j) sacc[i][j] = 0.f;

        #pragma unroll
        for (int kk = 0; kk < 8; ++kk) {
            int k0 = kk * 8;
            uint32_t a0 = __float_as_uint(Qs[(wq + r4)     * APITCH + k0 + cc]);
            uint32_t a1 = __float_as_uint(Qs[(wq + r4 + 8) * APITCH + k0 + cc]);
            uint32_t a2 = __float_as_uint(Qs[(wq + r4)     * APITCH + k0 + cc + 4]);
            uint32_t a3 = __float_as_uint(Qs[(wq + r4 + 8) * APITCH + k0 + cc + 4]);
            #pragma unroll
            for (int nt = 0; nt < 8; ++nt) {
                uint32_t b0 = __float_as_uint(Ks[(nt * 8 + r4) * APITCH + k0 + cc]);
                uint32_t b1 = __float_as_uint(Ks[(nt * 8 + r4) * APITCH + k0 + cc + 4]);
                mma_tf32(sacc[nt], a0, a1, a2, a3, b0, b1);
            }
        }

        float mlo = -1e30f, mhi = -1e30f;
        #pragma unroll
        for (int nt = 0; nt < 8; ++nt) {
            sacc[nt][0] *= scale; sacc[nt][1] *= scale;
            sacc[nt][2] *= scale; sacc[nt][3] *= scale;
            mlo = fmaxf(mlo, fmaxf(sacc[nt][0], sacc[nt][1]));
            mhi = fmaxf(mhi, fmaxf(sacc[nt][2], sacc[nt][3]));
        }
        mlo = fmaxf(mlo, __shfl_xor_sync(0xffffffffu, mlo, 1));
        mlo = fmaxf(mlo, __shfl_xor_sync(0xffffffffu, mlo, 2));
        mhi = fmaxf(mhi, __shfl_xor_sync(0xffffffffu, mhi, 1));
        mhi = fmaxf(mhi, __shfl_xor_sync(0xffffffffu, mhi, 2));
        float mn_lo = fmaxf(mr_lo, mlo), mn_hi = fmaxf(mr_hi, mhi);
        float al_lo = __expf(mr_lo - mn_lo), al_hi = __expf(mr_hi - mn_hi);

        float ps_lo = 0.f, ps_hi = 0.f;
        #pragma unroll
        for (int nt = 0; nt < 8; ++nt) {
            float p0 = __expf(sacc[nt][0] - mn_lo);
            float p1 = __expf(sacc[nt][1] - mn_lo);
            float p2 = __expf(sacc[nt][2] - mn_hi);
            float p3 = __expf(sacc[nt][3] - mn_hi);
            ps_lo += p0 + p1; ps_hi += p2 + p3;
            int colb = nt * 8 + cc * 2;
            Ps[(wq + r4)     * APITCH + colb]     = tf32r(p0);
            Ps[(wq + r4)     * APITCH + colb + 1] = tf32r(p1);
            Ps[(wq + r4 + 8) * APITCH + colb]     = tf32r(p2);
            Ps[(wq + r4 + 8) * APITCH + colb + 1] = tf32r(p3);
        }
        ps_lo += __shfl_xor_sync(0xffffffffu, ps_lo, 1);
        ps_lo += __shfl_xor_sync(0xffffffffu, ps_lo, 2);
        ps_hi += __shfl_xor_sync(0xffffffffu, ps_hi, 1);
        ps_hi += __shfl_xor_sync(0xffffffffu, ps_hi, 2);
        l_lo = l_lo * al_lo + ps_lo;
        l_hi = l_hi * al_hi + ps_hi;
        mr_lo = mn_lo; mr_hi = mn_hi;
        #pragma unroll
        for (int nt = 0; nt < 8; ++nt) {
            oacc[nt][0] *= al_lo; oacc[nt][1] *= al_lo;
            oacc[nt][2] *= al_hi; oacc[nt][3] *= al_hi;
        }
        __syncwarp();

        #pragma unroll
        for (int kk = 0; kk < 8; ++kk) {
            int k0 = kk * 8;
            uint32_t a0 = __float_as_uint(Ps[(wq + r4)     * APITCH + k0 + cc]);
            uint32_t a1 = __float_as_uint(Ps[(wq + r4 + 8) * APITCH + k0 + cc]);
            uint32_t a2 = __float_as_uint(Ps[(wq + r4)     * APITCH + k0 + cc + 4]);
            uint32_t a3 = __float_as_uint(Ps[(wq + r4 + 8) * APITCH + k0 + cc + 4]);
            #pragma unroll
            for (int nt = 0; nt < 8; ++nt) {
                uint32_t b0 = __float_as_uint(Vs[(k0 + cc)     * APITCH + nt * 8 + r4]);
                uint32_t b1 = __float_as_uint(Vs[(k0 + cc + 4) * APITCH + nt * 8 + r4]);
                mma_tf32(oacc[nt], a0, a1, a2, a3, b0, b1);
            }
        }
    }

    float il_lo = 1.f / l_lo, il_hi = 1.f / l_hi;
    int row_lo = b * 1024 + s0 + wq + r4;
    #pragma unroll
    for (int nt = 0; nt < 8; ++nt) {
        int col = h * HEAD_D + nt * 8 + cc * 2;
        *(float2*)&ctx[(size_t)row_lo * D_MODEL + col] =
            make_float2(tf32r(oacc[nt][0] * il_lo), tf32r(oacc[nt][1] * il_lo));
        *(float2*)&ctx[(size_t)(row_lo + 8) * D_MODEL + col] =
            make_float2(tf32r(oacc[nt][2] * il_hi), tf32r(oacc[nt][3] * il_hi));
    }
}

// ---------------- launch ----------------
extern "C" void kernel_launch(void* const* d_in, const int* in_sizes, int n_in,
                              void* d_out, int out_size) {
    const float* x      = (const float*)d_in[0];
    const float* qkv_w  = (const float*)d_in[1];
    const float* qkv_b  = (const float*)d_in[2];
    const float* proj_w = (const float*)d_in[3];
    const float* proj_b = (const float*)d_in[4];
    const float* fc1_w  = (const float*)d_in[5];
    const float* fc1_b  = (const float*)d_in[6];
    const float* fc2_w  = (const float*)d_in[7];
    const float* fc2_b  = (const float*)d_in[8];
    const float* ln1_g  = (const float*)d_in[9];
    const float* ln1_b  = (const float*)d_in[10];
    const float* ln2_g  = (const float*)d_in[11];
    const float* ln2_b  = (const float*)d_in[12];
    float* out = (float*)d_out;

    float *h, *qkv, *ctx, *x2, *ff, *wq, *wp, *w1, *w2;
    cudaGetSymbolAddress((void**)&h,   g_h);
    cudaGetSymbolAddress((void**)&qkv, g_qkv);
    cudaGetSymbolAddress((void**)&ctx, g_ctx);
    cudaGetSymbolAddress((void**)&x2,  g_x2);
    cudaGetSymbolAddress((void**)&ff,  g_ff);
    cudaGetSymbolAddress((void**)&wq,  g_wq);
    cudaGetSymbolAddress((void**)&wp,  g_wp);
    cudaGetSymbolAddress((void**)&w1,  g_w1);
    cudaGetSymbolAddress((void**)&w2,  g_w2);

    int attn_smem = 4 * 64 * APITCH * (int)sizeof(float);
    cudaFuncSetAttribute(attn_tc, cudaFuncAttributeMaxDynamicSharedMemorySize,
                         attn_smem);
    int gemm_smem = STAGES * STAGE_BYTES;   // 81920
    cudaFuncSetAttribute(gemm_cp<0,0>, cudaFuncAttributeMaxDynamicSharedMemorySize, gemm_smem);
    cudaFuncSetAttribute(gemm_cp<2,0>, cudaFuncAttributeMaxDynamicSharedMemorySize, gemm_smem);
    cudaFuncSetAttribute(gemm_cp<1,1>, cudaFuncAttributeMaxDynamicSharedMemorySize, gemm_smem);

    // pre-round weights to tf32
    round_w<<<(3*D_MODEL*D_MODEL/4 + 255)/256, 256>>>(qkv_w, wq, 3*D_MODEL*D_MODEL/4);
    round_w<<<(D_MODEL*D_MODEL/4 + 255)/256, 256>>>(proj_w, wp, D_MODEL*D_MODEL/4);
    round_w<<<(FF_DIM*D_MODEL/4 + 255)/256, 256>>>(fc1_w, w1, FF_DIM*D_MODEL/4);
    round_w<<<(D_MODEL*FF_DIM/4 + 255)/256, 256>>>(fc2_w, w2, D_MODEL*FF_DIM/4);

    ln_kernel<<<N_TOK, 256>>>(x, ln1_g, ln1_b, h);
    gemm_cp<0,0><<<dim3(3 * D_MODEL / BN, N_TOK / BM), 256, gemm_smem>>>(
        h, wq, qkv_b, nullptr, qkv, N_TOK, 3 * D_MODEL, D_MODEL);
    attn_tc<<<dim3(1024 / 64, N_HEAD, 8), 128, attn_smem>>>(qkv, ctx);
    gemm_cp<2,0><<<dim3(D_MODEL / BN, N_TOK / BM), 256, gemm_smem>>>(
        ctx, wp, proj_b, x, x2, N_TOK, D_MODEL, D_MODEL);
    ln_kernel<<<N_TOK, 256>>>(x2, ln2_g, ln2_b, h);
    gemm_cp<1,1><<<dim3(FF_DIM / BN, N_TOK / BM), 256, gemm_smem>>>(
        h, w1, fc1_b, nullptr, ff, N_TOK, FF_DIM, D_MODEL);
    gemm_cp<2,0><<<dim3(D_MODEL / BN, N_TOK / BM), 256, gemm_smem>>>(
        ff, w2, fc2_b, x2, out, N_TOK, D_MODEL, FF_DIM);
}